// round 15
// baseline (speedup 1.0000x reference)
#include <cuda_runtime.h>
#include <cuda_bf16.h>
#include <cuda_fp16.h>
#include <math.h>
#include <stdint.h>

// Problem dims
#define SEQ_LEN 12
#define BATCH   512
#define NG      16
#define GROUP   32
#define HD      128      // H
#define ED      64       // E
#define PRE     512
#define BOTTLE  1024
#define MLPD    1024
#define GATES   (4*HD)   // 512
#define KCAT    (ED+HD)  // 192
#define ROWS_PN (NG*GROUP*GROUP)  // 16384
#define DHK     (HD+BOTTLE)       // 1152

// ---------------- scratch (device globals; no allocation) ----------------
__device__ float g_h[BATCH*HD];
__device__ float g_c[BATCH*HD];
__device__ float g_pos[BATCH*2];
__device__ __align__(16) __half g_deh[SEQ_LEN*BATCH*ED];  // dec_in fp16 hi, all steps
__device__ __align__(16) __half g_del[SEQ_LEN*BATCH*ED];  // dec_in fp16 lo, all steps
__device__ __align__(16) __half g_Wch[GATES*KCAT];      // Wcat fp16 hi
__device__ __align__(16) __half g_Wcl[GATES*KCAT];      // Wcat fp16 lo
__device__ float g_bsum[GATES];
__device__ float g_gates[BATCH*GATES];
__device__ __align__(16) __half g_hh16[BATCH*HD];       // h fp16 hi limb (tracks current h)
__device__ __align__(16) __half g_hl16[BATCH*HD];       // h fp16 lo limb
__device__ __align__(16) __half g_W1hh[PRE*HD];         // W1 h-part fp16
__device__ __align__(16) __half g_W1eh[PRE*ED];         // W1 emb-part fp16
__device__ float g_hW1h[BATCH*PRE];
__device__ __align__(16) __half g_X1h[ROWS_PN*PRE];     // X1 fp16
__device__ __align__(16) __half g_W2h[BOTTLE*PRE];      // W2 fp16
__device__ __align__(16) __half g_dch[BATCH*DHK];       // dcat fp16 = [h | pool]
__device__ __align__(16) __half g_Wm1h[MLPD*DHK];       // Wm1 fp16
__device__ float g_D1[BATCH*MLPD];
__device__ float g_sqacc[BATCH];

__device__ __forceinline__ float sigmoidf(float x) { return 1.0f / (1.0f + expf(-x)); }

// ---------------- PTX helpers (base-arch only: sm_80+ features) ----------------
__device__ __forceinline__ uint32_t smem_u32(const void* p) {
    uint32_t a;
    asm("{ .reg .u64 t; cvta.to.shared.u64 t, %1; cvt.u32.u64 %0, t; }" : "=r"(a) : "l"(p));
    return a;
}
__device__ __forceinline__ void cp_async16(uint32_t s, const void* g) {
    asm volatile("cp.async.cg.shared.global [%0], [%1], 16;" :: "r"(s), "l"(g));
}
#define CP_COMMIT() asm volatile("cp.async.commit_group;" ::: "memory")
#define CP_WAIT1()  asm volatile("cp.async.wait_group 1;" ::: "memory")
#define CP_WAIT0()  asm volatile("cp.async.wait_group 0;" ::: "memory")

__device__ __forceinline__ void ldmatrix_x4(uint32_t* r, uint32_t addr) {
    asm volatile("ldmatrix.sync.aligned.m8n8.x4.shared.b16 {%0,%1,%2,%3}, [%4];"
                 : "=r"(r[0]), "=r"(r[1]), "=r"(r[2]), "=r"(r[3]) : "r"(addr));
}
__device__ __forceinline__ void mma_f16(float* c, const uint32_t* a, uint32_t b0, uint32_t b1) {
    asm volatile("mma.sync.aligned.m16n8k16.row.col.f32.f16.f16.f32 "
                 "{%0,%1,%2,%3}, {%4,%5,%6,%7}, {%8,%9}, {%0,%1,%2,%3};"
                 : "+f"(c[0]), "+f"(c[1]), "+f"(c[2]), "+f"(c[3])
                 : "r"(a[0]), "r"(a[1]), "r"(a[2]), "r"(a[3]), "r"(b0), "r"(b1));
}

// ---------------- init ----------------
__global__ void init_kernel(const float* __restrict__ hh, const float* __restrict__ ch,
                            const float* __restrict__ last_pos,
                            const float* __restrict__ Wih, const float* __restrict__ Whh,
                            const float* __restrict__ bih, const float* __restrict__ bhh,
                            const float* __restrict__ W1, const float* __restrict__ W2,
                            const float* __restrict__ Wm1) {
    int idx = blockIdx.x * blockDim.x + threadIdx.x;
    if (idx < BATCH*HD) {
        float h = hh[idx];
        g_h[idx] = h; g_c[idx] = ch[idx];
        __half hv = __float2half(h);
        g_hh16[idx] = hv;
        g_hl16[idx] = __float2half(h - __half2float(hv));
    }
    if (idx < BATCH*2)  g_pos[idx] = last_pos[idx];
    if (idx < BATCH)    g_sqacc[idx] = 0.0f;
    if (idx < GATES) g_bsum[idx] = bih[idx] + bhh[idx];
    if (idx < GATES*KCAT) {
        int n = idx / KCAT, k = idx % KCAT;
        float w = (k < ED) ? Wih[n*ED + k] : Whh[n*HD + (k - ED)];
        __half hi = __float2half(w);
        g_Wch[idx] = hi;
        g_Wcl[idx] = __float2half(w - __half2float(hi));
    }
    if (idx < PRE*ED) {
        int n = idx >> 6, k = idx & 63;
        g_W1eh[idx] = __float2half(W1[n*KCAT + k]);
    }
    if (idx < PRE*HD) {
        int n = idx >> 7, k = idx & 127;
        g_W1hh[idx] = __float2half(W1[n*KCAT + ED + k]);
    }
    if (idx < BOTTLE*PRE) g_W2h[idx] = __float2half(W2[idx]);
    if (idx < MLPD*DHK)   g_Wm1h[idx] = __float2half(Wm1[idx]);
}

// Precompute dec_in spatial embeddings for ALL steps (teacher forcing is static).
__global__ void decall_kernel(const float* __restrict__ last_pos_rel,
                              const float* __restrict__ pred_traj_rel,
                              const float* __restrict__ Wse, const float* __restrict__ bse) {
    int idx = blockIdx.x * blockDim.x + threadIdx.x;
    if (idx >= SEQ_LEN*BATCH*ED) return;
    int t = idx / (BATCH*ED);
    int r = idx % (BATCH*ED);
    int b = r / ED, e = r % ED;
    const float* rel = (t == 0) ? (last_pos_rel + b*2)
                                : (pred_traj_rel + ((size_t)(t-1)*BATCH + b)*2);
    float v = rel[0] * Wse[e*2] + rel[1] * Wse[e*2+1] + bse[e];
    __half hi = __float2half(v);
    g_deh[idx] = hi;
    g_del[idx] = __float2half(v - __half2float(hi));
}

// ---------------- fused LSTM elementwise + rel_pos + pos + loss accum ----------------
__global__ void lstm_pos_kernel(const float* __restrict__ Wpos, const float* __restrict__ bpos,
                                const float* __restrict__ gt, float* __restrict__ out_pred) {
    int b = blockIdx.x, j = threadIdx.x;
    const float* gr = g_gates + b*GATES;
    float ig = gr[j], fg = gr[HD + j], gg = gr[2*HD + j], og = gr[3*HD + j];
    float c = sigmoidf(fg) * g_c[b*HD + j] + sigmoidf(ig) * tanhf(gg);
    float h = sigmoidf(og) * tanhf(c);
    g_c[b*HD + j] = c;
    __half hhv = __float2half(h);
    g_hh16[b*HD + j] = hhv;
    g_hl16[b*HD + j] = __float2half(h - __half2float(hhv));
    g_dch[(size_t)b*DHK + j] = hhv;

    __shared__ float sx[HD], sy[HD];
    sx[j] = h * Wpos[j];
    sy[j] = h * Wpos[HD + j];
    __syncthreads();
    for (int s = HD/2; s > 0; s >>= 1) {
        if (j < s) { sx[j] += sx[j + s]; sy[j] += sy[j + s]; }
        __syncthreads();
    }
    if (j == 0) {
        float rx = sx[0] + bpos[0], ry = sy[0] + bpos[1];
        out_pred[b*2]   = rx;
        out_pred[b*2+1] = ry;
        g_pos[b*2]   += rx;
        g_pos[b*2+1] += ry;
        float dx = rx - gt[b*2], dy = ry - gt[b*2+1];
        g_sqacc[b] += dx*dx + dy*dy;
    }
}

__global__ void finish_kernel(float* __restrict__ out, int out_size) {
    __shared__ float sd[BATCH];
    int t = threadIdx.x;
    sd[t] = g_sqacc[t];
    __syncthreads();
    for (int s = BATCH/2; s > 0; s >>= 1) {
        if (t < s) sd[t] += sd[t + s];
        __syncthreads();
    }
    if (t == 0 && out_size > SEQ_LEN*BATCH*2)
        out[SEQ_LEN*BATCH*2] = sd[0] / (float)(BATCH*2);
}

// ---------------- D2: h = relu(D1 @ Wm2^T + bm2); ALSO emits post-MLP h fp16 limbs ----------------
__global__ void d2_kernel(const float* __restrict__ A, const float* __restrict__ W,
                          const float* __restrict__ bias) {
    __shared__ float As[64][17];
    __shared__ float Ws[64][17];
    int tid = threadIdx.x;
    int m0 = blockIdx.y * 64, n0 = blockIdx.x * 64;
    int ty = tid >> 4, tx = tid & 15;
    float acc[4][4] = {};

    for (int k0 = 0; k0 < MLPD; k0 += 16) {
        #pragma unroll
        for (int l = tid; l < 64*16; l += 256) {
            int r = l >> 4, c = l & 15;
            As[r][c] = A[(m0 + r) * MLPD + k0 + c];
            Ws[r][c] = W[(n0 + r) * MLPD + k0 + c];
        }
        __syncthreads();
        #pragma unroll
        for (int kk = 0; kk < 16; kk++) {
            float a[4], w[4];
            #pragma unroll
            for (int i = 0; i < 4; i++) { a[i] = As[ty*4 + i][kk]; w[i] = Ws[tx*4 + i][kk]; }
            #pragma unroll
            for (int i = 0; i < 4; i++)
                #pragma unroll
                for (int j = 0; j < 4; j++) acc[i][j] += a[i] * w[j];
        }
        __syncthreads();
    }

    #pragma unroll
    for (int i = 0; i < 4; i++) {
        int m = m0 + ty*4 + i;
        #pragma unroll
        for (int j = 0; j < 4; j++) {
            int n = n0 + tx*4 + j;
            float v = fmaxf(acc[i][j] + bias[n], 0.0f);
            g_h[m*HD + n] = v;
            __half hv = __float2half(v);
            g_hh16[m*HD + n] = hv;
            g_hl16[m*HD + n] = __float2half(v - __half2float(hv));
        }
    }
}

#define HG_LDA 72

// ---------------- HMMA gates: gates = [dec_in|h] @ Wcat^T + bsum (3-term fp16) ----------------
#define GT_A    (64 * HG_LDA * 2)
#define GT_B    (128 * HG_LDA * 2)
#define GT_DYN  (2*GT_A + 2*GT_B)      // 55296

__global__ void __launch_bounds__(256, 1)
hgemm_gates(int t) {
    extern __shared__ char dyn[];
    const int tid  = threadIdx.x;
    const int lane = tid & 31;
    const int wid  = tid >> 5;
    const int wm   = wid >> 2;
    const int wn   = wid & 3;
    const int n0 = blockIdx.x * 128;
    const int m0 = blockIdx.y * 64;

    uint32_t sAh = smem_u32(dyn);
    uint32_t sAl = sAh + GT_A;
    uint32_t sBh = sAl + GT_A;
    uint32_t sBl = sBh + GT_B;
    float acc[2][4][4] = {};

    const int a_row  = wm * 32 + (lane & 15);
    const int a_colg = (lane >> 4) * 8;
    const int b_sub  = ((lane >> 4) & 1) * 8 + (lane & 7);
    const int b_colg = ((lane >> 3) & 1) * 8;

    for (int c = 0; c < 3; c++) {
        int kc = c * 64;
        const __half *Ah, *Al;
        int lda;
        if (c == 0) {
            Ah = g_deh + (size_t)t*BATCH*ED + (size_t)m0 * ED;
            Al = g_del + (size_t)t*BATCH*ED + (size_t)m0 * ED;
            lda = ED;
        } else {
            Ah = g_hh16 + (size_t)m0 * HD + (c - 1) * 64;
            Al = g_hl16 + (size_t)m0 * HD + (c - 1) * 64;
            lda = HD;
        }
        const __half* Bh = g_Wch + (size_t)n0 * KCAT + kc;
        const __half* Bl = g_Wcl + (size_t)n0 * KCAT + kc;
        #pragma unroll
        for (int u = 0; u < 2; u++) {
            int idx = tid + u * 256;
            int row = idx >> 3, seg = idx & 7;
            uint32_t off = (uint32_t)(row * HG_LDA + seg * 8) * 2;
            cp_async16(sAh + off, Ah + (size_t)row * lda + seg * 8);
            cp_async16(sAl + off, Al + (size_t)row * lda + seg * 8);
        }
        #pragma unroll
        for (int u = 0; u < 4; u++) {
            int idx = tid + u * 256;
            int row = idx >> 3, seg = idx & 7;
            uint32_t off = (uint32_t)(row * HG_LDA + seg * 8) * 2;
            cp_async16(sBh + off, Bh + (size_t)row * KCAT + seg * 8);
            cp_async16(sBl + off, Bl + (size_t)row * KCAT + seg * 8);
        }
        CP_COMMIT();
        CP_WAIT0();
        __syncthreads();

        #pragma unroll
        for (int ks = 0; ks < 4; ks++) {
            uint32_t bh[2][4], bl[2][4];
            #pragma unroll
            for (int nf2 = 0; nf2 < 2; nf2++) {
                uint32_t ro = (uint32_t)((wn*32 + nf2*16 + b_sub) * HG_LDA + ks*16 + b_colg) * 2;
                ldmatrix_x4(bh[nf2], sBh + ro);
                ldmatrix_x4(bl[nf2], sBl + ro);
            }
            uint32_t ah[2][4], al[2][4];
            #pragma unroll
            for (int mf = 0; mf < 2; mf++) {
                uint32_t ro = (uint32_t)((a_row + mf*16) * HG_LDA + ks*16 + a_colg) * 2;
                ldmatrix_x4(ah[mf], sAh + ro);
                ldmatrix_x4(al[mf], sAl + ro);
            }
            #pragma unroll
            for (int mf = 0; mf < 2; mf++)
                #pragma unroll
                for (int nf = 0; nf < 4; nf++) {
                    uint32_t bh0 = bh[nf>>1][(nf&1)*2], bh1 = bh[nf>>1][(nf&1)*2 + 1];
                    uint32_t bl0 = bl[nf>>1][(nf&1)*2], bl1 = bl[nf>>1][(nf&1)*2 + 1];
                    mma_f16(acc[mf][nf], ah[mf], bh0, bh1);
                    mma_f16(acc[mf][nf], ah[mf], bl0, bl1);
                    mma_f16(acc[mf][nf], al[mf], bh0, bh1);
                }
        }
        __syncthreads();
    }

    #pragma unroll
    for (int mf = 0; mf < 2; mf++) {
        int R  = m0 + wm*32 + mf*16 + (lane >> 2);
        int R8 = R + 8;
        #pragma unroll
        for (int nf = 0; nf < 4; nf++) {
            int n = n0 + wn*32 + nf*8 + (lane & 3)*2;
            float b0 = g_bsum[n], b1v = g_bsum[n + 1];
            g_gates[(size_t)R  * GATES + n]     = acc[mf][nf][0] + b0;
            g_gates[(size_t)R  * GATES + n + 1] = acc[mf][nf][1] + b1v;
            g_gates[(size_t)R8 * GATES + n]     = acc[mf][nf][2] + b0;
            g_gates[(size_t)R8 * GATES + n + 1] = acc[mf][nf][3] + b1v;
        }
    }
}

// ---------------- HMMA hW1h: hW1h = h @ W1h^T (h 2-limb x W1h fp16) ----------------
#define HW_A    (64 * HG_LDA * 2)
#define HW_B    (128 * HG_LDA * 2)
#define HW_DYN  (2*HW_A + HW_B)

__global__ void __launch_bounds__(256, 1)
hgemm_hw1h() {
    extern __shared__ char dyn[];
    const int tid  = threadIdx.x;
    const int lane = tid & 31;
    const int wid  = tid >> 5;
    const int wm   = wid >> 2;
    const int wn   = wid & 3;
    const int n0 = blockIdx.x * 128;
    const int m0 = blockIdx.y * 64;

    uint32_t sAh = smem_u32(dyn);
    uint32_t sAl = sAh + HW_A;
    uint32_t sB  = sAl + HW_A;
    float acc[2][4][4] = {};

    const int a_row  = wm * 32 + (lane & 15);
    const int a_colg = (lane >> 4) * 8;
    const int b_sub  = ((lane >> 4) & 1) * 8 + (lane & 7);
    const int b_colg = ((lane >> 3) & 1) * 8;

    for (int c = 0; c < 2; c++) {
        int kc = c * 64;
        const __half* Ah = g_hh16 + (size_t)m0 * HD + kc;
        const __half* Al = g_hl16 + (size_t)m0 * HD + kc;
        const __half* Bp = g_W1hh + (size_t)n0 * HD + kc;
        #pragma unroll
        for (int u = 0; u < 2; u++) {
            int idx = tid + u * 256;
            int row = idx >> 3, seg = idx & 7;
            uint32_t off = (uint32_t)(row * HG_LDA + seg * 8) * 2;
            cp_async16(sAh + off, Ah + (size_t)row * HD + seg * 8);
            cp_async16(sAl + off, Al + (size_t)row * HD + seg * 8);
        }
        #pragma unroll
        for (int u = 0; u < 4; u++) {
            int idx = tid + u * 256;
            int row = idx >> 3, seg = idx & 7;
            cp_async16(sB + (uint32_t)(row * HG_LDA + seg * 8) * 2,
                       Bp + (size_t)row * HD + seg * 8);
        }
        CP_COMMIT();
        CP_WAIT0();
        __syncthreads();

        #pragma unroll
        for (int ks = 0; ks < 4; ks++) {
            uint32_t bfr[2][4];
            #pragma unroll
            for (int nf2 = 0; nf2 < 2; nf2++)
                ldmatrix_x4(bfr[nf2], sB + (uint32_t)((wn*32 + nf2*16 + b_sub) * HG_LDA + ks*16 + b_colg) * 2);
            uint32_t ah[2][4], al[2][4];
            #pragma unroll
            for (int mf = 0; mf < 2; mf++) {
                uint32_t ro = (uint32_t)((a_row + mf*16) * HG_LDA + ks*16 + a_colg) * 2;
                ldmatrix_x4(ah[mf], sAh + ro);
                ldmatrix_x4(al[mf], sAl + ro);
            }
            #pragma unroll
            for (int mf = 0; mf < 2; mf++)
                #pragma unroll
                for (int nf = 0; nf < 4; nf++) {
                    uint32_t b0 = bfr[nf>>1][(nf&1)*2], b1 = bfr[nf>>1][(nf&1)*2 + 1];
                    mma_f16(acc[mf][nf], ah[mf], b0, b1);
                    mma_f16(acc[mf][nf], al[mf], b0, b1);
                }
        }
        __syncthreads();
    }

    #pragma unroll
    for (int mf = 0; mf < 2; mf++) {
        int R  = m0 + wm*32 + mf*16 + (lane >> 2);
        int R8 = R + 8;
        #pragma unroll
        for (int nf = 0; nf < 4; nf++) {
            int n = n0 + wn*32 + nf*8 + (lane & 3)*2;
            g_hW1h[(size_t)R  * PRE + n]     = acc[mf][nf][0];
            g_hW1h[(size_t)R  * PRE + n + 1] = acc[mf][nf][1];
            g_hW1h[(size_t)R8 * PRE + n]     = acc[mf][nf][2];
            g_hW1h[(size_t)R8 * PRE + n + 1] = acc[mf][nf][3];
        }
    }
}

// ---------------- X1 HMMA with FUSED emb computation ----------------
// A-tiles (emb fp16 hi/lo limbs) are computed in-kernel from g_pos/Wp/bp directly
// into smem (identical fp32 expression as the old emb_kernel -> bit-identical limbs).
// CTA 256x128, 8 warps (4x2), warp 64x64, K=64, single-stage.
#define X1_AH      (256 * HG_LDA * 2)
#define X1_B       (128 * HG_LDA * 2)
#define X1_DYN     (2 * X1_AH + X1_B)   // 92160

__global__ void __launch_bounds__(256, 1)
hgemm_x1(const float* __restrict__ Wp, const float* __restrict__ bp,
         const float* __restrict__ bias, const float* __restrict__ aux) {
    extern __shared__ char dyn[];
    __shared__ float sWp[2*ED];
    __shared__ float sbp[ED];
    const int tid  = threadIdx.x;
    const int lane = tid & 31;
    const int wid  = tid >> 5;
    const int wm   = wid >> 1;
    const int wn   = wid & 1;
    const int n0 = blockIdx.x * 128;
    const int m0 = blockIdx.y * 256;

    uint32_t sbase = smem_u32(dyn);
    uint32_t sAh = sbase;
    uint32_t sAl = sAh + X1_AH;
    uint32_t sB  = sAl + X1_AH;
    __half* pAh = reinterpret_cast<__half*>(dyn);
    __half* pAl = reinterpret_cast<__half*>(dyn + X1_AH);
    float acc[4][8][4] = {};

    const int a_row  = wm * 64 + (lane & 15);
    const int a_colg = (lane >> 4) * 8;
    const int b_sub  = ((lane >> 4) & 1) * 8 + (lane & 7);
    const int b_colg = ((lane >> 3) & 1) * 8;

    // B load via cp.async; A limbs computed in-kernel.
    {
        const __half* Bp = g_W1eh + (size_t)n0 * ED;
        #pragma unroll
        for (int u = 0; u < 4; u++) {
            int idx = tid + u * 256;          // 0..1023
            int row = idx >> 3, seg = idx & 7;
            cp_async16(sB + (uint32_t)(row * HG_LDA + seg * 8) * 2,
                       Bp + (size_t)row * ED + seg * 8);
        }
        CP_COMMIT();

        if (tid < 2*ED) sWp[tid] = Wp[tid];
        else if (tid < 3*ED) sbp[tid - 2*ED] = bp[tid - 2*ED];
        __syncthreads();

        // Compute emb limbs: 256 rows x 64 cols, 2 cols (half2) per thread-iter.
        #pragma unroll
        for (int u = 0; u < 32; u++) {
            int idx = tid + u * 256;          // 0..8191
            int row = idx >> 5;               // 0..255
            int c2  = idx & 31;               // half2 column pair
            int R = m0 + row;
            int g = R >> 10, ii = (R >> 5) & 31, jj = R & 31;
            float2 pi = *reinterpret_cast<const float2*>(&g_pos[(g*GROUP + ii)*2]);
            float2 pj = *reinterpret_cast<const float2*>(&g_pos[(g*GROUP + jj)*2]);
            float rx = pj.x - pi.x, ry = pj.y - pi.y;
            int e = c2 * 2;
            float v0 = rx * sWp[e*2]     + ry * sWp[e*2 + 1] + sbp[e];
            float v1 = rx * sWp[e*2 + 2] + ry * sWp[e*2 + 3] + sbp[e + 1];
            __half h0 = __float2half(v0), h1 = __float2half(v1);
            __half2 hh; hh.x = h0; hh.y = h1;
            __half2 hl;
            hl.x = __float2half(v0 - __half2float(h0));
            hl.y = __float2half(v1 - __half2float(h1));
            int off = row * HG_LDA + e;
            *reinterpret_cast<__half2*>(&pAh[off]) = hh;
            *reinterpret_cast<__half2*>(&pAl[off]) = hl;
        }
        CP_WAIT0();
        __syncthreads();
    }

    #pragma unroll
    for (int ks = 0; ks < 4; ks++) {
        uint32_t bfr[4][4];
        #pragma unroll
        for (int nf2 = 0; nf2 < 4; nf2++)
            ldmatrix_x4(bfr[nf2], sB + (uint32_t)((wn*64 + nf2*16 + b_sub) * HG_LDA + ks*16 + b_colg) * 2);
        {
            uint32_t afr[4][4];
            #pragma unroll
            for (int mf = 0; mf < 4; mf++)
                ldmatrix_x4(afr[mf], sAh + (uint32_t)((a_row + mf*16) * HG_LDA + ks*16 + a_colg) * 2);
            #pragma unroll
            for (int mf = 0; mf < 4; mf++)
                #pragma unroll
                for (int nf = 0; nf < 8; nf++)
                    mma_f16(acc[mf][nf], afr[mf], bfr[nf>>1][(nf&1)*2], bfr[nf>>1][(nf&1)*2 + 1]);
        }
        {
            uint32_t afr[4][4];
            #pragma unroll
            for (int mf = 0; mf < 4; mf++)
                ldmatrix_x4(afr[mf], sAl + (uint32_t)((a_row + mf*16) * HG_LDA + ks*16 + a_colg) * 2);
            #pragma unroll
            for (int mf = 0; mf < 4; mf++)
                #pragma unroll
                for (int nf = 0; nf < 8; nf++)
                    mma_f16(acc[mf][nf], afr[mf], bfr[nf>>1][(nf&1)*2], bfr[nf>>1][(nf&1)*2 + 1]);
        }
    }

    #pragma unroll
    for (int mf = 0; mf < 4; mf++) {
        int R  = m0 + wm*64 + mf*16 + (lane >> 2);
        int R8 = R + 8;
        const float* aux0 = aux + (size_t)((R  >> 10)*32 + (R  & 31)) * PRE;
        const float* aux8 = aux + (size_t)((R8 >> 10)*32 + (R8 & 31)) * PRE;
        #pragma unroll
        for (int nf = 0; nf < 8; nf++) {
            int n = n0 + wn*64 + nf*8 + (lane & 3)*2;
            float b0 = bias[n], b1v = bias[n + 1];
            float v0 = fmaxf(acc[mf][nf][0] + b0  + aux0[n],     0.0f);
            float v1 = fmaxf(acc[mf][nf][1] + b1v + aux0[n + 1], 0.0f);
            float v2 = fmaxf(acc[mf][nf][2] + b0  + aux8[n],     0.0f);
            float v3 = fmaxf(acc[mf][nf][3] + b1v + aux8[n + 1], 0.0f);
            __half2 h01, h23;
            h01.x = __float2half(v0); h01.y = __float2half(v1);
            h23.x = __float2half(v2); h23.y = __float2half(v3);
            *reinterpret_cast<__half2*>(&g_X1h[(size_t)R  * PRE + n]) = h01;
            *reinterpret_cast<__half2*>(&g_X1h[(size_t)R8 * PRE + n]) = h23;
        }
    }
}

// ---------------- fp16 GEMM2 (256x128 CTA, 8 warps 4x2, warp 64x64) ----------------
// pool-part of dcat = relu(max_j(X1 @ W2^T) + b2) written as fp16 to g_dch[:, HD:].
#define G2_A       (256 * HG_LDA * 2)    // 36864
#define G2_B       (128 * HG_LDA * 2)    // 18432
#define G2_STG     (G2_A + G2_B)         // 55296
#define G2_DYN     (2 * G2_STG)          // 110592

__global__ void __launch_bounds__(256, 1)
gemm2_f16(const float* __restrict__ b2) {
    extern __shared__ char dyn[];
    const int tid  = threadIdx.x;
    const int lane = tid & 31;
    const int wid  = tid >> 5;
    const int wm   = wid >> 1;      // 0..3
    const int wn   = wid & 1;       // 0..1
    const int n0 = blockIdx.x * 128;
    const int m0 = blockIdx.y * 256;

    uint32_t sbase = smem_u32(dyn);
    float acc[4][8][4] = {};

    const int a_row  = wm * 64 + (lane & 15);
    const int a_colg = (lane >> 4) * 8;
    const int b_sub  = ((lane >> 4) & 1) * 8 + (lane & 7);
    const int b_colg = ((lane >> 3) & 1) * 8;

    auto load_chunk = [&](int c, int s) {
        int kc = c * 64;
        const __half* Ap = g_X1h + (size_t)m0 * PRE + kc;
        const __half* Bp = g_W2h + (size_t)n0 * PRE + kc;
        uint32_t sA = sbase + s * G2_STG;
        uint32_t sB = sA + G2_A;
        #pragma unroll
        for (int u = 0; u < 8; u++) {
            int idx = tid + u * 256;
            int row = idx >> 3, seg = idx & 7;
            cp_async16(sA + (uint32_t)(row * HG_LDA + seg * 8) * 2,
                       Ap + (size_t)row * PRE + seg * 8);
        }
        #pragma unroll
        for (int u = 0; u < 4; u++) {
            int idx = tid + u * 256;
            int row = idx >> 3, seg = idx & 7;
            cp_async16(sB + (uint32_t)(row * HG_LDA + seg * 8) * 2,
                       Bp + (size_t)row * PRE + seg * 8);
        }
    };

    load_chunk(0, 0);
    CP_COMMIT();

    for (int c = 0; c < 8; c++) {
        if (c + 1 < 8) { load_chunk(c + 1, (c + 1) & 1); CP_COMMIT(); CP_WAIT1(); }
        else CP_WAIT0();
        __syncthreads();

        uint32_t sA = sbase + (c & 1) * G2_STG;
        uint32_t sB = sA + G2_A;
        #pragma unroll
        for (int ks = 0; ks < 4; ks++) {
            uint32_t bfr[4][4];
            #pragma unroll
            for (int nf2 = 0; nf2 < 4; nf2++)
                ldmatrix_x4(bfr[nf2], sB + (uint32_t)((wn*64 + nf2*16 + b_sub) * HG_LDA + ks*16 + b_colg) * 2);
            uint32_t afr[4][4];
            #pragma unroll
            for (int mf = 0; mf < 4; mf++)
                ldmatrix_x4(afr[mf], sA + (uint32_t)((a_row + mf*16) * HG_LDA + ks*16 + a_colg) * 2);
            #pragma unroll
            for (int mf = 0; mf < 4; mf++)
                #pragma unroll
                for (int nf = 0; nf < 8; nf++)
                    mma_f16(acc[mf][nf], afr[mf], bfr[nf>>1][(nf&1)*2], bfr[nf>>1][(nf&1)*2 + 1]);
        }
        __syncthreads();
    }

    #pragma unroll
    for (int half = 0; half < 2; half++) {
        int pr = blockIdx.y * 8 + wm * 2 + half;    // pool row = m/32
        #pragma unroll
        for (int nf = 0; nf < 8; nf++) {
            float v0 = fmaxf(fmaxf(acc[2*half][nf][0], acc[2*half][nf][2]),
                             fmaxf(acc[2*half+1][nf][0], acc[2*half+1][nf][2]));
            float v1 = fmaxf(fmaxf(acc[2*half][nf][1], acc[2*half][nf][3]),
                             fmaxf(acc[2*half+1][nf][1], acc[2*half+1][nf][3]));
            #pragma unroll
            for (int d = 4; d < 32; d <<= 1) {
                v0 = fmaxf(v0, __shfl_xor_sync(0xffffffffu, v0, d));
                v1 = fmaxf(v1, __shfl_xor_sync(0xffffffffu, v1, d));
            }
            if ((lane >> 2) == 0) {
                int n = n0 + wn*64 + nf*8 + (lane & 3)*2;
                __half2 hv;
                hv.x = __float2half(fmaxf(v0 + b2[n],     0.0f));
                hv.y = __float2half(fmaxf(v1 + b2[n + 1], 0.0f));
                *reinterpret_cast<__half2*>(&g_dch[(size_t)pr * DHK + HD + n]) = hv;
            }
        }
    }
}

// ---------------- fp16 D1: D1 = relu(dcat @ Wm1^T + bm1) ----------------
#define D1_A    (64 * HG_LDA * 2)
#define D1_B    (128 * HG_LDA * 2)
#define D1_STG  (D1_A + D1_B)
#define D1_DYN  (2 * D1_STG)

__global__ void __launch_bounds__(256, 1)
hgemm_d1(const float* __restrict__ bias) {
    extern __shared__ char dyn[];
    const int tid  = threadIdx.x;
    const int lane = tid & 31;
    const int wid  = tid >> 5;
    const int wm   = wid >> 2;
    const int wn   = wid & 3;
    const int n0 = blockIdx.x * 128;
    const int m0 = blockIdx.y * 64;

    uint32_t sbase = smem_u32(dyn);
    float acc[2][4][4] = {};

    const int a_row  = wm * 32 + (lane & 15);
    const int a_colg = (lane >> 4) * 8;
    const int b_sub  = ((lane >> 4) & 1) * 8 + (lane & 7);
    const int b_colg = ((lane >> 3) & 1) * 8;

    auto load_chunk = [&](int c, int s) {
        int kc = c * 64;
        const __half* Ap = g_dch + (size_t)m0 * DHK + kc;
        const __half* Bp = g_Wm1h + (size_t)n0 * DHK + kc;
        uint32_t sA = sbase + s * D1_STG;
        uint32_t sB = sA + D1_A;
        #pragma unroll
        for (int u = 0; u < 2; u++) {
            int idx = tid + u * 256;
            int row = idx >> 3, seg = idx & 7;
            cp_async16(sA + (uint32_t)(row * HG_LDA + seg * 8) * 2,
                       Ap + (size_t)row * DHK + seg * 8);
        }
        #pragma unroll
        for (int u = 0; u < 4; u++) {
            int idx = tid + u * 256;
            int row = idx >> 3, seg = idx & 7;
            cp_async16(sB + (uint32_t)(row * HG_LDA + seg * 8) * 2,
                       Bp + (size_t)row * DHK + seg * 8);
        }
    };

    load_chunk(0, 0);
    CP_COMMIT();

    for (int c = 0; c < 18; c++) {
        if (c + 1 < 18) { load_chunk(c + 1, (c + 1) & 1); CP_COMMIT(); CP_WAIT1(); }
        else CP_WAIT0();
        __syncthreads();

        uint32_t sA = sbase + (c & 1) * D1_STG;
        uint32_t sB = sA + D1_A;
        #pragma unroll
        for (int ks = 0; ks < 4; ks++) {
            uint32_t bfr[2][4];
            #pragma unroll
            for (int nf2 = 0; nf2 < 2; nf2++)
                ldmatrix_x4(bfr[nf2], sB + (uint32_t)((wn*32 + nf2*16 + b_sub) * HG_LDA + ks*16 + b_colg) * 2);
            uint32_t afr[2][4];
            #pragma unroll
            for (int mf = 0; mf < 2; mf++)
                ldmatrix_x4(afr[mf], sA + (uint32_t)((a_row + mf*16) * HG_LDA + ks*16 + a_colg) * 2);
            #pragma unroll
            for (int mf = 0; mf < 2; mf++)
                #pragma unroll
                for (int nf = 0; nf < 4; nf++)
                    mma_f16(acc[mf][nf], afr[mf], bfr[nf>>1][(nf&1)*2], bfr[nf>>1][(nf&1)*2 + 1]);
        }
        __syncthreads();
    }

    #pragma unroll
    for (int mf = 0; mf < 2; mf++) {
        int R  = m0 + wm*32 + mf*16 + (lane >> 2);
        int R8 = R + 8;
        #pragma unroll
        for (int nf = 0; nf < 4; nf++) {
            int n = n0 + wn*32 + nf*8 + (lane & 3)*2;
            float b0 = bias[n], b1v = bias[n + 1];
            g_D1[(size_t)R  * MLPD + n]     = fmaxf(acc[mf][nf][0] + b0,  0.0f);
            g_D1[(size_t)R  * MLPD + n + 1] = fmaxf(acc[mf][nf][1] + b1v, 0.0f);
            g_D1[(size_t)R8 * MLPD + n]     = fmaxf(acc[mf][nf][2] + b0,  0.0f);
            g_D1[(size_t)R8 * MLPD + n + 1] = fmaxf(acc[mf][nf][3] + b1v, 0.0f);
        }
    }
}

// ---------------- launch ----------------
extern "C" void kernel_launch(void* const* d_in, const int* in_sizes, int n_in,
                              void* d_out, int out_size) {
    const float* last_pos      = (const float*)d_in[0];
    const float* last_pos_rel  = (const float*)d_in[1];
    const float* hh            = (const float*)d_in[2];
    const float* ch            = (const float*)d_in[3];
    const float* pred_traj_rel = (const float*)d_in[4];
    const float* W_ih = (const float*)d_in[6];
    const float* W_hh = (const float*)d_in[7];
    const float* b_ih = (const float*)d_in[8];
    const float* b_hh = (const float*)d_in[9];
    const float* Wse  = (const float*)d_in[10];
    const float* bse  = (const float*)d_in[11];
    const float* Wpos = (const float*)d_in[12];
    const float* bpos = (const float*)d_in[13];
    const float* Wp   = (const float*)d_in[14];
    const float* bp   = (const float*)d_in[15];
    const float* W1   = (const float*)d_in[16];
    const float* b1   = (const float*)d_in[17];
    const float* W2   = (const float*)d_in[18];
    const float* b2   = (const float*)d_in[19];
    const float* Wm1  = (const float*)d_in[20];
    const float* bm1  = (const float*)d_in[21];
    const float* Wm2  = (const float*)d_in[22];
    const float* bm2  = (const float*)d_in[23];

    float* out = (float*)d_out;

    float* p_hW1h  = nullptr; cudaGetSymbolAddress((void**)&p_hW1h,  g_hW1h);
    float* p_D1    = nullptr; cudaGetSymbolAddress((void**)&p_D1,    g_D1);

    cudaFuncSetAttribute(hgemm_gates, cudaFuncAttributeMaxDynamicSharedMemorySize, GT_DYN);
    cudaFuncSetAttribute(hgemm_hw1h,  cudaFuncAttributeMaxDynamicSharedMemorySize, HW_DYN);
    cudaFuncSetAttribute(hgemm_x1,    cudaFuncAttributeMaxDynamicSharedMemorySize, X1_DYN);
    cudaFuncSetAttribute(gemm2_f16,   cudaFuncAttributeMaxDynamicSharedMemorySize, G2_DYN);
    cudaFuncSetAttribute(hgemm_d1,    cudaFuncAttributeMaxDynamicSharedMemorySize, D1_DYN);

    init_kernel<<<(MLPD*DHK + 255)/256, 256>>>(hh, ch, last_pos,
                                               W_ih, W_hh, b_ih, b_hh, W1, W2, Wm1);
    decall_kernel<<<(SEQ_LEN*BATCH*ED + 255)/256, 256>>>(last_pos_rel, pred_traj_rel, Wse, bse);

    for (int t = 0; t < SEQ_LEN; t++) {
        const float* gt = pred_traj_rel + t * BATCH * 2;
        float* out_pred = out + t * BATCH * 2;

        // LSTM cell: HMMA gates (reads post-MLP h limbs) -> fused elementwise/pos/loss
        hgemm_gates<<<dim3(GATES/128, BATCH/64), 256, GT_DYN>>>(t);
        lstm_pos_kernel<<<BATCH, HD>>>(Wpos, bpos, gt, out_pred);

        // pool net (hw1h uses pre-MLP h limbs; X1 computes emb in-kernel from g_pos)
        hgemm_hw1h<<<dim3(PRE/128, BATCH/64), 256, HW_DYN>>>();
        hgemm_x1<<<dim3(PRE/128, ROWS_PN/256), 256, X1_DYN>>>(Wp, bp, b1, p_hW1h);
        gemm2_f16<<<dim3(BOTTLE/128, ROWS_PN/256), 256, G2_DYN>>>(b2);

        // decoder MLP; D2 emits post-MLP h (fp32 + fp16 limbs) for next step's gates
        hgemm_d1<<<dim3(MLPD/128, BATCH/64), 256, D1_DYN>>>(bm1);
        d2_kernel<<<dim3(HD/64, BATCH/64), 256>>>(p_D1, Wm2, bm2);
    }

    finish_kernel<<<1, BATCH>>>(out, out_size);
}